// round 13
// baseline (speedup 1.0000x reference)
#include <cuda_runtime.h>
#include <cuda_bf16.h>
#include <cuda_fp16.h>
#include <cstdint>
#include <cmath>

#define NROW 4096
#define ZD   2048
#define TWO_N 8192
#define TM_TILE 128
#define TN_TILE 128
#define TKS 64                       // fp8 elems per stage = 64 B rows
#define NKSTG (ZD / TKS)             // 32 stages
#define STAGES 4
#define STAGE_BYTES (2 * TM_TILE * 64)    // A(8KB) + B(8KB) = 16KB
#define SMEM_TOTAL (STAGES * STAGE_BYTES) // 64 KB dynamic -> 3 CTAs/SM
#define NTILE 64
#define NUM_TILES ((NTILE * (NTILE + 1)) / 2)   // 2080
#define GRID_CTAS 444                // 3 per SM x 148 SMs
#define FP8_SCALE 16.0f
#define EPI_SCALE 0.0078125f         // logits = acc/128

// ---------------- scratch ----------------------------------------------------
__device__ __align__(256) uint8_t g_reps[(size_t)TWO_N * ZD];   // 16 MB e4m3
__device__ float g_rowsum[TWO_N];
__device__ float g_pos[NROW];
__device__ int g_counter;
__device__ int g_done;

// ---------------- helpers ----------------------------------------------------
__device__ __forceinline__ uint32_t smem_u32(const void* p) {
    uint32_t a;
    asm("{ .reg .u64 t; cvta.to.shared.u64 t, %1; cvt.u32.u64 %0, t; }" : "=r"(a) : "l"(p));
    return a;
}
// 64B-row swizzle: chunk(bits[4:6)) ^= (row>>1)&3 (row bits at [7:9))
#define SWZ64(bo) ((bo) ^ (((bo) >> 3) & 0x30))
#define CP_ASYNC16(dst, src) \
    asm volatile("cp.async.cg.shared.global [%0], [%1], 16;" :: "r"(dst), "l"(src))
#define CP_COMMIT() asm volatile("cp.async.commit_group;" ::: "memory")
#define CP_WAIT2()  asm volatile("cp.async.wait_group 2;" ::: "memory")

__device__ __forceinline__ void ldmatrix_x4(uint32_t& r0, uint32_t& r1,
                                            uint32_t& r2, uint32_t& r3, uint32_t addr) {
    asm volatile("ldmatrix.sync.aligned.m8n8.x4.shared.b16 {%0,%1,%2,%3}, [%4];"
                 : "=r"(r0), "=r"(r1), "=r"(r2), "=r"(r3) : "r"(addr));
}
__device__ __forceinline__ void mma_fp8_h(uint32_t* c, const uint32_t* a,
                                          uint32_t b0, uint32_t b1) {
    asm volatile("mma.sync.aligned.m16n8k32.row.col.f16.e4m3.e4m3.f16 "
                 "{%0,%1}, {%2,%3,%4,%5}, {%6,%7}, {%0,%1};"
                 : "+r"(c[0]), "+r"(c[1])
                 : "r"(a[0]), "r"(a[1]), "r"(a[2]), "r"(a[3]), "r"(b0), "r"(b1));
}
__device__ __forceinline__ uint16_t cvt_e4m3x2(float hi, float lo) {
    uint16_t d;
    asm("cvt.rn.satfinite.e4m3x2.f32 %0, %1, %2;" : "=h"(d) : "f"(hi), "f"(lo));
    return d;
}

// ---------------- kernel 1: normalize + pos + fp8 quantize -----------------
__global__ void __launch_bounds__(256) k_prep(const float* __restrict__ z1,
                                              const float* __restrict__ z2) {
    int row = blockIdx.x;
    int t = threadIdx.x, lane = t & 31, wid = t >> 5;
    if (row == 0 && t == 0) { g_counter = 0; g_done = 0; }
    const float4* p1 = reinterpret_cast<const float4*>(z1) + (size_t)row * (ZD / 4);
    const float4* p2 = reinterpret_cast<const float4*>(z2) + (size_t)row * (ZD / 4);
    float4 a[2], b[2];
    a[0] = p1[2 * t]; a[1] = p1[2 * t + 1];
    b[0] = p2[2 * t]; b[1] = p2[2 * t + 1];
    const float* af = reinterpret_cast<const float*>(a);
    const float* bf = reinterpret_cast<const float*>(b);
    float s1 = 0.f, s2 = 0.f, sd = 0.f;
    #pragma unroll
    for (int i = 0; i < 8; i++) { s1 += af[i] * af[i]; s2 += bf[i] * bf[i]; sd += af[i] * bf[i]; }
    #pragma unroll
    for (int o = 16; o > 0; o >>= 1) {
        s1 += __shfl_xor_sync(0xFFFFFFFF, s1, o);
        s2 += __shfl_xor_sync(0xFFFFFFFF, s2, o);
        sd += __shfl_xor_sync(0xFFFFFFFF, sd, o);
    }
    __shared__ float red[3][8];
    if (lane == 0) { red[0][wid] = s1; red[1][wid] = s2; red[2][wid] = sd; }
    __syncthreads();
    float t1 = 0.f, t2 = 0.f, td = 0.f;
    #pragma unroll
    for (int w = 0; w < 8; w++) { t1 += red[0][w]; t2 += red[1][w]; td += red[2][w]; }
    float r1 = rsqrtf(t1) * FP8_SCALE, r2 = rsqrtf(t2) * FP8_SCALE;
    if (t == 0) {
        g_pos[row] = td * rsqrtf(t1) * rsqrtf(t2) * 2.0f;   // /T, T=0.5 (exact fp32)
        g_rowsum[row] = 0.f;
        g_rowsum[row + NROW] = 0.f;
    }
    uint16_t qa[4], qb[4];
    #pragma unroll
    for (int i = 0; i < 4; i++) {
        qa[i] = cvt_e4m3x2(af[2 * i + 1] * r1, af[2 * i] * r1);
        qb[i] = cvt_e4m3x2(bf[2 * i + 1] * r2, bf[2 * i] * r2);
    }
    uint2 va, vb;
    va.x = (uint32_t)qa[0] | ((uint32_t)qa[1] << 16);
    va.y = (uint32_t)qa[2] | ((uint32_t)qa[3] << 16);
    vb.x = (uint32_t)qb[0] | ((uint32_t)qb[1] << 16);
    vb.y = (uint32_t)qb[2] | ((uint32_t)qb[3] << 16);
    *reinterpret_cast<uint2*>(g_reps + (size_t)row * ZD + 8 * t)          = va;
    *reinterpret_cast<uint2*>(g_reps + (size_t)(row + NROW) * ZD + 8 * t) = vb;
}

// ---------------- kernel 2: persistent FP8 GEMM (4-stage ring) + final -----
__global__ void __launch_bounds__(256, 3) k_gemm(float* __restrict__ out) {
    extern __shared__ unsigned char smem[];
    uint32_t smem_base = smem_u32(smem);
    __shared__ int s_idx;
    const int tid = threadIdx.x, lane = tid & 31, wid = tid >> 5;
    const int wm = wid & 1, wn = wid >> 1;    // warp grid 2 (M) x 4 (N)

    // cp.async: thread -> row (tid&127), 2 chunks of 16B for A and B each
    const int lrow_g = tid & 127;
    const int chalf = (tid >> 7) * 2;         // chunk base 0 or 2
    uint32_t sdst[2];
    #pragma unroll
    for (int c = 0; c < 2; c++) {
        uint32_t bo = (uint32_t)(lrow_g * 64 + (chalf + c) * 16);
        sdst[c] = SWZ64(bo);
    }
    const int arow_l = ((lane >> 3) & 1) * 8 + (lane & 7);
    const int abyte_l = ((lane >> 4) & 1) * 16;
    const int brow_l = ((lane >> 4) & 1) * 8 + (lane & 7);
    const int bbyte_l = ((lane >> 3) & 1) * 16;

    for (;;) {
        __syncthreads();                       // smem stages + s_idx free
        if (tid == 0) s_idx = atomicAdd(&g_counter, 1);
        __syncthreads();
        const int idx = s_idx;
        if (idx >= NUM_TILES) break;

        int tm = (int)((129.0f - sqrtf(129.0f * 129.0f - 8.0f * (float)idx)) * 0.5f);
        if (tm < 0) tm = 0;
        if (tm > NTILE - 1) tm = NTILE - 1;
        while ((NTILE * (tm + 1) - ((tm + 1) * tm) / 2) <= idx) tm++;
        while ((NTILE * tm - (tm * (tm - 1)) / 2) > idx) tm--;
        const int tn = tm + (idx - (NTILE * tm - (tm * (tm - 1)) / 2));
        const bool diag = (tn == tm);

        const uint8_t* gArow = g_reps + (size_t)(tm * TM_TILE + lrow_g) * ZD + chalf * 16;
        const uint8_t* gBrow = g_reps + (size_t)(tn * TN_TILE + lrow_g) * ZD + chalf * 16;

        auto load_stage = [&](int s, int ks) {
            uint32_t sa = smem_base + s * STAGE_BYTES;
            const uint8_t* a = gArow + ks * TKS;
            const uint8_t* b = gBrow + ks * TKS;
            #pragma unroll
            for (int c = 0; c < 2; c++) {
                CP_ASYNC16(sa + sdst[c], a + c * 16);
                CP_ASYNC16(sa + 8192 + sdst[c], b + c * 16);
            }
        };

        load_stage(0, 0); CP_COMMIT();
        load_stage(1, 1); CP_COMMIT();
        load_stage(2, 2); CP_COMMIT();

        uint32_t acc[4][4][2];
        #pragma unroll
        for (int i = 0; i < 4; i++)
            #pragma unroll
            for (int j = 0; j < 4; j++) { acc[i][j][0] = 0u; acc[i][j][1] = 0u; }

        for (int ks = 0; ks < NKSTG; ks++) {
            CP_WAIT2();                        // stage ks landed (ks+1, ks+2 may pend)
            __syncthreads();                   // visibility + compute(ks-1) done everywhere
            if (ks + 3 < NKSTG) load_stage((ks + 3) & 3, ks + 3);   // overwrites buf (ks-1)&3
            CP_COMMIT();

            uint32_t sa = smem_base + (ks & 3) * STAGE_BYTES;
            uint32_t sb = sa + 8192;

            #pragma unroll
            for (int kk = 0; kk < 2; kk++) {   // 2 x k32 per stage
                uint32_t afr[4][4];
                #pragma unroll
                for (int i = 0; i < 4; i++) {
                    int row = wm * 64 + i * 16 + arow_l;
                    uint32_t bo = (uint32_t)(row * 64 + kk * 32 + abyte_l);
                    ldmatrix_x4(afr[i][0], afr[i][1], afr[i][2], afr[i][3], sa + SWZ64(bo));
                }
                uint32_t bfr[2][4];
                #pragma unroll
                for (int p = 0; p < 2; p++) {
                    int row = wn * 32 + p * 16 + brow_l;
                    uint32_t bo = (uint32_t)(row * 64 + kk * 32 + bbyte_l);
                    ldmatrix_x4(bfr[p][0], bfr[p][1], bfr[p][2], bfr[p][3], sb + SWZ64(bo));
                }
                #pragma unroll
                for (int i = 0; i < 4; i++) {
                    #pragma unroll
                    for (int j = 0; j < 4; j++) {
                        uint32_t b0 = bfr[j >> 1][(j & 1) * 2];
                        uint32_t b1 = bfr[j >> 1][(j & 1) * 2 + 1];
                        mma_fp8_h(acc[i][j], afr[i], b0, b1);
                    }
                }
            }
        }

        // epilogue
        const int rowbase = tm * TM_TILE + wm * 64;
        const int colbase = tn * TN_TILE + wn * 32;
        float rsum[4][2], csum[4][2];
        #pragma unroll
        for (int i = 0; i < 4; i++) { rsum[i][0] = 0.f; rsum[i][1] = 0.f; }
        #pragma unroll
        for (int j = 0; j < 4; j++) { csum[j][0] = 0.f; csum[j][1] = 0.f; }

        #pragma unroll
        for (int i = 0; i < 4; i++) {
            #pragma unroll
            for (int j = 0; j < 4; j++) {
                #pragma unroll
                for (int h = 0; h < 2; h++) {
                    float2 v2 = __half22float2(*reinterpret_cast<__half2*>(&acc[i][j][h]));
                    #pragma unroll
                    for (int c = 0; c < 2; c++) {
                        float e = __expf(EPI_SCALE * (c ? v2.y : v2.x));
                        if (diag) {
                            int grow = rowbase + i * 16 + (lane >> 2) + h * 8;
                            int gcol = colbase + j * 8 + (lane & 3) * 2 + c;
                            if (grow == gcol) e = 0.f;
                        }
                        rsum[i][h] += e;
                        csum[j][c] += e;
                    }
                }
            }
        }
        #pragma unroll
        for (int i = 0; i < 4; i++) {
            #pragma unroll
            for (int h = 0; h < 2; h++) {
                float v = rsum[i][h];
                v += __shfl_xor_sync(0xFFFFFFFF, v, 1);
                v += __shfl_xor_sync(0xFFFFFFFF, v, 2);
                if ((lane & 3) == 0)
                    atomicAdd(&g_rowsum[rowbase + i * 16 + (lane >> 2) + h * 8], v);
            }
        }
        if (!diag) {
            #pragma unroll
            for (int j = 0; j < 4; j++) {
                #pragma unroll
                for (int c = 0; c < 2; c++) {
                    float v = csum[j][c];
                    v += __shfl_xor_sync(0xFFFFFFFF, v, 4);
                    v += __shfl_xor_sync(0xFFFFFFFF, v, 8);
                    v += __shfl_xor_sync(0xFFFFFFFF, v, 16);
                    if (lane < 4)
                        atomicAdd(&g_rowsum[colbase + j * 8 + lane * 2 + c], v);
                }
            }
        }
    }

    // ---------------- fused finalization (last CTA) -------------------------
    __shared__ int s_last;
    __threadfence();
    __syncthreads();
    if (tid == 0) s_last = (atomicAdd(&g_done, 1) == GRID_CTAS - 1) ? 1 : 0;
    __syncthreads();
    if (s_last) {
        __threadfence();
        float acc = 0.f;
        for (int r = tid; r < TWO_N; r += 256)
            acc += logf(g_rowsum[r]) - g_pos[r & (NROW - 1)];
        #pragma unroll
        for (int o = 16; o > 0; o >>= 1) acc += __shfl_xor_sync(0xFFFFFFFF, acc, o);
        __shared__ float red[8];
        if ((tid & 31) == 0) red[tid >> 5] = acc;
        __syncthreads();
        if (tid == 0) {
            float tot = 0.f;
            #pragma unroll
            for (int w = 0; w < 8; w++) tot += red[w];
            out[0] = tot / (float)TWO_N;
        }
    }
}

// ---------------- launch ----------------------------------------------------
extern "C" void kernel_launch(void* const* d_in, const int* in_sizes, int n_in,
                              void* d_out, int out_size) {
    const float* z1 = (const float*)d_in[0];
    const float* z2 = (const float*)d_in[1];
    float* out = (float*)d_out;

    cudaFuncSetAttribute(k_gemm, cudaFuncAttributeMaxDynamicSharedMemorySize, SMEM_TOTAL);

    k_prep<<<NROW, 256>>>(z1, z2);
    k_gemm<<<GRID_CTAS, 256, SMEM_TOTAL>>>(out);
}

// round 14
// speedup vs baseline: 1.0625x; 1.0625x over previous
#include <cuda_runtime.h>
#include <cuda_bf16.h>
#include <cuda_fp16.h>
#include <cstdint>
#include <cmath>

#define NROW 4096
#define ZD   2048
#define TWO_N 8192
#define TM_TILE 128
#define TN_TILE 128
#define TKS 128                      // fp8 elems per stage = 128 B rows
#define NKSTG (ZD / TKS)             // 16 stages
#define STAGES 2
#define STAGE_BYTES (2 * TM_TILE * 128)   // A(16KB) + B(16KB)
#define SMEM_TOTAL (STAGES * STAGE_BYTES) // 64 KB dynamic -> 3 CTAs/SM
#define NTILE 64
#define NUM_TILES ((NTILE * (NTILE + 1)) / 2)   // 2080
#define GRID_CTAS 444                // 3 per SM x 148 SMs
#define FP8_SCALE 16.0f
#define EPI_SCALE 0.0078125f         // logits = acc/128

// ---------------- scratch ----------------------------------------------------
__device__ __align__(256) uint8_t g_reps[(size_t)TWO_N * ZD];   // 16 MB e4m3
__device__ float g_rowsum[TWO_N];
__device__ float g_pos[NROW];
__device__ int g_counter;
__device__ int g_done;

// ---------------- helpers ----------------------------------------------------
__device__ __forceinline__ uint32_t smem_u32(const void* p) {
    uint32_t a;
    asm("{ .reg .u64 t; cvta.to.shared.u64 t, %1; cvt.u32.u64 %0, t; }" : "=r"(a) : "l"(p));
    return a;
}
#define SWZ(bo) ((bo) ^ (((bo) >> 3) & 0x70))
#define CP_ASYNC16(dst, src) \
    asm volatile("cp.async.cg.shared.global [%0], [%1], 16;" :: "r"(dst), "l"(src))
#define CP_COMMIT() asm volatile("cp.async.commit_group;" ::: "memory")
#define CP_WAIT1()  asm volatile("cp.async.wait_group 1;" ::: "memory")

__device__ __forceinline__ void ldmatrix_x4(uint32_t& r0, uint32_t& r1,
                                            uint32_t& r2, uint32_t& r3, uint32_t addr) {
    asm volatile("ldmatrix.sync.aligned.m8n8.x4.shared.b16 {%0,%1,%2,%3}, [%4];"
                 : "=r"(r0), "=r"(r1), "=r"(r2), "=r"(r3) : "r"(addr));
}
__device__ __forceinline__ void mma_fp8_h(uint32_t* c, const uint32_t* a,
                                          uint32_t b0, uint32_t b1) {
    asm volatile("mma.sync.aligned.m16n8k32.row.col.f16.e4m3.e4m3.f16 "
                 "{%0,%1}, {%2,%3,%4,%5}, {%6,%7}, {%0,%1};"
                 : "+r"(c[0]), "+r"(c[1])
                 : "r"(a[0]), "r"(a[1]), "r"(a[2]), "r"(a[3]), "r"(b0), "r"(b1));
}
__device__ __forceinline__ uint16_t cvt_e4m3x2(float hi, float lo) {
    uint16_t d;
    asm("cvt.rn.satfinite.e4m3x2.f32 %0, %1, %2;" : "=h"(d) : "f"(hi), "f"(lo));
    return d;
}

// ---------------- kernel 1: normalize + pos + fp8 quantize -----------------
__global__ void __launch_bounds__(256) k_prep(const float* __restrict__ z1,
                                              const float* __restrict__ z2) {
    int row = blockIdx.x;
    int t = threadIdx.x, lane = t & 31, wid = t >> 5;
    if (row == 0 && t == 0) { g_counter = 0; g_done = 0; }
    const float4* p1 = reinterpret_cast<const float4*>(z1) + (size_t)row * (ZD / 4);
    const float4* p2 = reinterpret_cast<const float4*>(z2) + (size_t)row * (ZD / 4);
    float4 a[2], b[2];
    a[0] = p1[2 * t]; a[1] = p1[2 * t + 1];
    b[0] = p2[2 * t]; b[1] = p2[2 * t + 1];
    const float* af = reinterpret_cast<const float*>(a);
    const float* bf = reinterpret_cast<const float*>(b);
    float s1 = 0.f, s2 = 0.f, sd = 0.f;
    #pragma unroll
    for (int i = 0; i < 8; i++) { s1 += af[i] * af[i]; s2 += bf[i] * bf[i]; sd += af[i] * bf[i]; }
    #pragma unroll
    for (int o = 16; o > 0; o >>= 1) {
        s1 += __shfl_xor_sync(0xFFFFFFFF, s1, o);
        s2 += __shfl_xor_sync(0xFFFFFFFF, s2, o);
        sd += __shfl_xor_sync(0xFFFFFFFF, sd, o);
    }
    __shared__ float red[3][8];
    if (lane == 0) { red[0][wid] = s1; red[1][wid] = s2; red[2][wid] = sd; }
    __syncthreads();
    float t1 = 0.f, t2 = 0.f, td = 0.f;
    #pragma unroll
    for (int w = 0; w < 8; w++) { t1 += red[0][w]; t2 += red[1][w]; td += red[2][w]; }
    float r1 = rsqrtf(t1) * FP8_SCALE, r2 = rsqrtf(t2) * FP8_SCALE;
    if (t == 0) {
        g_pos[row] = td * rsqrtf(t1) * rsqrtf(t2) * 2.0f;   // /T, T=0.5 (exact fp32)
        g_rowsum[row] = 0.f;
        g_rowsum[row + NROW] = 0.f;
    }
    uint16_t qa[4], qb[4];
    #pragma unroll
    for (int i = 0; i < 4; i++) {
        qa[i] = cvt_e4m3x2(af[2 * i + 1] * r1, af[2 * i] * r1);
        qb[i] = cvt_e4m3x2(bf[2 * i + 1] * r2, bf[2 * i] * r2);
    }
    uint2 va, vb;
    va.x = (uint32_t)qa[0] | ((uint32_t)qa[1] << 16);
    va.y = (uint32_t)qa[2] | ((uint32_t)qa[3] << 16);
    vb.x = (uint32_t)qb[0] | ((uint32_t)qb[1] << 16);
    vb.y = (uint32_t)qb[2] | ((uint32_t)qb[3] << 16);
    *reinterpret_cast<uint2*>(g_reps + (size_t)row * ZD + 8 * t)          = va;
    *reinterpret_cast<uint2*>(g_reps + (size_t)(row + NROW) * ZD + 8 * t) = vb;
}

// ---------------- kernel 2: persistent FP8 GEMM (3 CTAs/SM) + final --------
__global__ void __launch_bounds__(256, 3) k_gemm(float* __restrict__ out) {
    extern __shared__ unsigned char smem[];
    uint32_t smem_base = smem_u32(smem);
    __shared__ int s_idx;
    const int tid = threadIdx.x, lane = tid & 31, wid = tid >> 5;
    const int wm = wid & 1, wn = wid >> 1;    // warp grid 2 (M) x 4 (N)

    const int lrow_g = tid & 127;
    const int cp = (tid >> 7) * 4;
    uint32_t sdst[4];
    #pragma unroll
    for (int c = 0; c < 4; c++) {
        uint32_t bo = (uint32_t)(lrow_g * 128 + (cp + c) * 16);
        sdst[c] = SWZ(bo);
    }
    const int arow_l = ((lane >> 3) & 1) * 8 + (lane & 7);
    const int abyte_l = ((lane >> 4) & 1) * 16;
    const int brow_l = ((lane >> 4) & 1) * 8 + (lane & 7);
    const int bbyte_l = ((lane >> 3) & 1) * 16;

    for (;;) {
        __syncthreads();                       // smem stages + s_idx free
        if (tid == 0) s_idx = atomicAdd(&g_counter, 1);
        __syncthreads();
        const int idx = s_idx;
        if (idx >= NUM_TILES) break;

        int tm = (int)((129.0f - sqrtf(129.0f * 129.0f - 8.0f * (float)idx)) * 0.5f);
        if (tm < 0) tm = 0;
        if (tm > NTILE - 1) tm = NTILE - 1;
        while ((NTILE * (tm + 1) - ((tm + 1) * tm) / 2) <= idx) tm++;
        while ((NTILE * tm - (tm * (tm - 1)) / 2) > idx) tm--;
        const int tn = tm + (idx - (NTILE * tm - (tm * (tm - 1)) / 2));
        const bool diag = (tn == tm);

        const uint8_t* gArow = g_reps + (size_t)(tm * TM_TILE + lrow_g) * ZD + cp * 16;
        const uint8_t* gBrow = g_reps + (size_t)(tn * TN_TILE + lrow_g) * ZD + cp * 16;

        auto load_stage = [&](int s, int ks) {
            uint32_t sa = smem_base + s * STAGE_BYTES;
            const uint8_t* a = gArow + ks * TKS;
            const uint8_t* b = gBrow + ks * TKS;
            #pragma unroll
            for (int c = 0; c < 4; c++) {
                CP_ASYNC16(sa + sdst[c], a + c * 16);
                CP_ASYNC16(sa + 16384 + sdst[c], b + c * 16);
            }
        };

        load_stage(0, 0); CP_COMMIT();
        load_stage(1, 1); CP_COMMIT();

        uint32_t acc[4][4][2];
        #pragma unroll
        for (int i = 0; i < 4; i++)
            #pragma unroll
            for (int j = 0; j < 4; j++) { acc[i][j][0] = 0u; acc[i][j][1] = 0u; }

        for (int ks = 0; ks < NKSTG; ks++) {
            CP_WAIT1();                        // stage ks landed
            __syncthreads();

            uint32_t sa = smem_base + (ks & 1) * STAGE_BYTES;
            uint32_t sb = sa + 16384;

            #pragma unroll
            for (int kk = 0; kk < 4; kk++) {
                uint32_t afr[4][4];
                #pragma unroll
                for (int i = 0; i < 4; i++) {
                    int row = wm * 64 + i * 16 + arow_l;
                    uint32_t bo = (uint32_t)(row * 128 + kk * 32 + abyte_l);
                    ldmatrix_x4(afr[i][0], afr[i][1], afr[i][2], afr[i][3], sa + SWZ(bo));
                }
                uint32_t bfr[2][4];
                #pragma unroll
                for (int p = 0; p < 2; p++) {
                    int row = wn * 32 + p * 16 + brow_l;
                    uint32_t bo = (uint32_t)(row * 128 + kk * 32 + bbyte_l);
                    ldmatrix_x4(bfr[p][0], bfr[p][1], bfr[p][2], bfr[p][3], sb + SWZ(bo));
                }
                #pragma unroll
                for (int i = 0; i < 4; i++) {
                    #pragma unroll
                    for (int j = 0; j < 4; j++) {
                        uint32_t b0 = bfr[j >> 1][(j & 1) * 2];
                        uint32_t b1 = bfr[j >> 1][(j & 1) * 2 + 1];
                        mma_fp8_h(acc[i][j], afr[i], b0, b1);
                    }
                }
            }
            __syncthreads();                   // done reading buf[ks&1]
            if (ks + 2 < NKSTG) load_stage(ks & 1, ks + 2);
            CP_COMMIT();
        }

        // epilogue
        const int rowbase = tm * TM_TILE + wm * 64;
        const int colbase = tn * TN_TILE + wn * 32;
        float rsum[4][2], csum[4][2];
        #pragma unroll
        for (int i = 0; i < 4; i++) { rsum[i][0] = 0.f; rsum[i][1] = 0.f; }
        #pragma unroll
        for (int j = 0; j < 4; j++) { csum[j][0] = 0.f; csum[j][1] = 0.f; }

        #pragma unroll
        for (int i = 0; i < 4; i++) {
            #pragma unroll
            for (int j = 0; j < 4; j++) {
                #pragma unroll
                for (int h = 0; h < 2; h++) {
                    float2 v2 = __half22float2(*reinterpret_cast<__half2*>(&acc[i][j][h]));
                    #pragma unroll
                    for (int c = 0; c < 2; c++) {
                        float e = __expf(EPI_SCALE * (c ? v2.y : v2.x));
                        if (diag) {
                            int grow = rowbase + i * 16 + (lane >> 2) + h * 8;
                            int gcol = colbase + j * 8 + (lane & 3) * 2 + c;
                            if (grow == gcol) e = 0.f;
                        }
                        rsum[i][h] += e;
                        csum[j][c] += e;
                    }
                }
            }
        }
        #pragma unroll
        for (int i = 0; i < 4; i++) {
            #pragma unroll
            for (int h = 0; h < 2; h++) {
                float v = rsum[i][h];
                v += __shfl_xor_sync(0xFFFFFFFF, v, 1);
                v += __shfl_xor_sync(0xFFFFFFFF, v, 2);
                if ((lane & 3) == 0)
                    atomicAdd(&g_rowsum[rowbase + i * 16 + (lane >> 2) + h * 8], v);
            }
        }
        if (!diag) {
            #pragma unroll
            for (int j = 0; j < 4; j++) {
                #pragma unroll
                for (int c = 0; c < 2; c++) {
                    float v = csum[j][c];
                    v += __shfl_xor_sync(0xFFFFFFFF, v, 4);
                    v += __shfl_xor_sync(0xFFFFFFFF, v, 8);
                    v += __shfl_xor_sync(0xFFFFFFFF, v, 16);
                    if (lane < 4)
                        atomicAdd(&g_rowsum[colbase + j * 8 + lane * 2 + c], v);
                }
            }
        }
    }

    // ---------------- fused finalization (last CTA) -------------------------
    __shared__ int s_last;
    __threadfence();
    __syncthreads();
    if (tid == 0) s_last = (atomicAdd(&g_done, 1) == GRID_CTAS - 1) ? 1 : 0;
    __syncthreads();
    if (s_last) {
        __threadfence();
        float acc = 0.f;
        for (int r = tid; r < TWO_N; r += 256)
            acc += logf(g_rowsum[r]) - g_pos[r & (NROW - 1)];
        #pragma unroll
        for (int o = 16; o > 0; o >>= 1) acc += __shfl_xor_sync(0xFFFFFFFF, acc, o);
        __shared__ float red[8];
        if ((tid & 31) == 0) red[tid >> 5] = acc;
        __syncthreads();
        if (tid == 0) {
            float tot = 0.f;
            #pragma unroll
            for (int w = 0; w < 8; w++) tot += red[w];
            out[0] = tot / (float)TWO_N;
        }
    }
}

// ---------------- launch ----------------------------------------------------
extern "C" void kernel_launch(void* const* d_in, const int* in_sizes, int n_in,
                              void* d_out, int out_size) {
    const float* z1 = (const float*)d_in[0];
    const float* z2 = (const float*)d_in[1];
    float* out = (float*)d_out;

    cudaFuncSetAttribute(k_gemm, cudaFuncAttributeMaxDynamicSharedMemorySize, SMEM_TOTAL);

    k_prep<<<NROW, 256>>>(z1, z2);
    k_gemm<<<GRID_CTAS, 256, SMEM_TOTAL>>>(out);
}